// round 5
// baseline (speedup 1.0000x reference)
#include <cuda_runtime.h>
#include <math.h>

#define NREV 4096
#define LTOK 128
#define DW   200
#define AASP 32
#define NNEG 5
#define BUSR 1024

// ---------------- scratch (device globals) -----------------------------------
__device__ __align__(16) float g_q[NREV * DW];
__device__ __align__(16) float g_rs[NREV * DW];
__device__ float g_hinge[NREV];
__device__ float g_sq[BUSR];
__device__ float g_U[1];

__device__ __forceinline__ float dot4(float4 a, float4 b) {
    return a.x * b.x + a.y * b.y + a.z * b.z + a.w * b.w;
}
__device__ __forceinline__ float warp_sum(float v) {
    #pragma unroll
    for (int o = 16; o; o >>= 1) v += __shfl_down_sync(0xffffffffu, v, o);
    return v;
}

// ---------------- K1: q = rev_pos @ M_w (vectorized) -------------------------
__global__ __launch_bounds__(256, 1)
void qk(const float* __restrict__ rp, const float* __restrict__ Mw) {
    extern __shared__ float sm[];
    float* Ms  = sm;            // 40000
    float* rps = sm + DW * DW;  // 6400
    int tid = threadIdx.x, w = tid >> 5, lane = tid & 31;
    for (int i = tid; i < DW * DW; i += 256) Ms[i] = Mw[i];
    int n0 = blockIdx.x * 32;
    for (int i = tid; i < 32 * DW; i += 256) rps[i] = rp[n0 * DW + i];
    __syncthreads();

    const float4* Ms4  = (const float4*)Ms;
    const float4* rps4 = (const float4*)rps;
    bool hi = (lane < 18);

    float4 acc[4][2];
    #pragma unroll
    for (int j = 0; j < 4; j++) {
        acc[j][0] = make_float4(0, 0, 0, 0);
        acc[j][1] = make_float4(0, 0, 0, 0);
    }

    for (int d2b = 0; d2b < 50; d2b++) {
        float4 r4[4];
        #pragma unroll
        for (int j = 0; j < 4; j++) r4[j] = rps4[(w * 4 + j) * 50 + d2b];
        #pragma unroll
        for (int s = 0; s < 4; s++) {
            int d2 = d2b * 4 + s;
            float4 m0 = Ms4[d2 * 50 + lane];
            float4 m1 = hi ? Ms4[d2 * 50 + 32 + lane] : make_float4(0, 0, 0, 0);
            #pragma unroll
            for (int j = 0; j < 4; j++) {
                float r = (s == 0) ? r4[j].x : (s == 1) ? r4[j].y : (s == 2) ? r4[j].z : r4[j].w;
                acc[j][0].x += r * m0.x; acc[j][0].y += r * m0.y;
                acc[j][0].z += r * m0.z; acc[j][0].w += r * m0.w;
                acc[j][1].x += r * m1.x; acc[j][1].y += r * m1.y;
                acc[j][1].z += r * m1.z; acc[j][1].w += r * m1.w;
            }
        }
    }
    float4* gq4 = (float4*)g_q;
    #pragma unroll
    for (int j = 0; j < 4; j++) {
        int row = (n0 + w * 4 + j) * 50;
        gq4[row + lane] = acc[j][0];
        if (hi) gq4[row + 32 + lane] = acc[j][1];
    }
}

// ---------------- K2: fused per-review ABAE, single gather + fp32 SMEM tile ---
// 384 threads (12 warps), occupancy 2 (24 warps/SM), ~106KB dynamic SMEM.
// SMEM floats: e 0..25599 | qs 25600 | ax 25800 | zs 25928 | p 26128 |
//              part 26160 (12*13) | tot 26316 | tok(int) 26332..26459
#define SM_WORDS 26460

__global__ __launch_bounds__(384, 2)
void mainkern(const int* __restrict__ hist, const float* __restrict__ wemb,
              const float* __restrict__ rneg, const float* __restrict__ Ww,
              const float* __restrict__ Wb, const float* __restrict__ Tw) {
    extern __shared__ float sm[];
    int n = blockIdx.x;
    int tid = threadIdx.x, w = tid >> 5, lane = tid & 31;

    // -------- extra block: U_loss --------
    if (n == NREV) {
        float* Ts  = sm;          // 6400
        float* nrm = sm + 6400;   // 32
        float* red = sm + 6432;   // 12
        for (int i = tid; i < DW * AASP; i += 384) Ts[i] = Tw[i];
        __syncthreads();
        if (tid < AASP) {
            float s = 0.f;
            for (int d = 0; d < DW; d++) { float v = Ts[d * AASP + tid]; s += v * v; }
            nrm[tid] = fmaxf(sqrtf(s), 1e-12f);
        }
        __syncthreads();
        float part = 0.f;
        for (int pr = tid; pr < AASP * AASP; pr += 384) {
            int a = pr >> 5, b = pr & 31;
            float s = 0.f;
            for (int d = 0; d < DW; d++) s += Ts[d * AASP + a] * Ts[d * AASP + b];
            float g = s / (nrm[a] * nrm[b]);
            float diff = g - ((a == b) ? 1.f : 0.f);
            part += diff * diff;
        }
        float v = warp_sum(part);
        if (lane == 0) red[w] = v;
        __syncthreads();
        if (tid == 0) {
            float t = 0.f;
            for (int k = 0; k < 12; k++) t += red[k];
            g_U[0] = t / (float)(AASP * AASP);
        }
        return;
    }

    float* e    = sm;
    float* qs   = sm + 25600;
    float* ax   = sm + 25800;
    float* zs   = sm + 25928;
    float* p    = sm + 26128;
    float* part = sm + 26160;
    float* tot  = sm + 26316;
    int*   tok  = (int*)(sm + 26332);

    if (tid < LTOK) tok[tid] = hist[n * LTOK + tid];
    if (tid < DW)   qs[tid]  = g_q[n * DW + tid];
    __syncthreads();

    bool hi = (lane < 18);
    const float4* qs4 = (const float4*)qs;
    float4 qv0 = qs4[lane];
    float4 qv1 = hi ? qs4[32 + lane] : make_float4(0, 0, 0, 0);
    const float4* we4 = (const float4*)wemb;
    float4* e4 = (float4*)e;

    // -------- single gather + dx: warp w owns tokens l = w + 12*i --------
    #pragma unroll
    for (int i0 = 0; i0 < 8; i0 += 4) {
        float4 v0[4], v1[4];
        #pragma unroll
        for (int t = 0; t < 4; t++) {
            int rb = tok[w + 12 * (i0 + t)] * 50;
            v0[t] = __ldg(&we4[rb + lane]);
            v1[t] = hi ? __ldg(&we4[rb + 32 + lane]) : make_float4(0, 0, 0, 0);
        }
        float a[4];
        #pragma unroll
        for (int t = 0; t < 4; t++) {
            int l = w + 12 * (i0 + t);
            e4[l * 50 + lane] = v0[t];
            if (hi) e4[l * 50 + 32 + lane] = v1[t];
            a[t] = dot4(v0[t], qv0) + dot4(v1[t], qv1);
        }
        #pragma unroll
        for (int t = 0; t < 4; t++) a[t] = warp_sum(a[t]);
        if (lane == 0) {
            #pragma unroll
            for (int t = 0; t < 4; t++) ax[w + 12 * (i0 + t)] = a[t];
        }
    }
    {   // i = 8, 9
        float4 v0[2], v1[2];
        #pragma unroll
        for (int t = 0; t < 2; t++) {
            int rb = tok[w + 12 * (8 + t)] * 50;
            v0[t] = __ldg(&we4[rb + lane]);
            v1[t] = hi ? __ldg(&we4[rb + 32 + lane]) : make_float4(0, 0, 0, 0);
        }
        float a[2];
        #pragma unroll
        for (int t = 0; t < 2; t++) {
            int l = w + 12 * (8 + t);
            e4[l * 50 + lane] = v0[t];
            if (hi) e4[l * 50 + 32 + lane] = v1[t];
            a[t] = dot4(v0[t], qv0) + dot4(v1[t], qv1);
        }
        #pragma unroll
        for (int t = 0; t < 2; t++) a[t] = warp_sum(a[t]);
        if (lane == 0) {
            #pragma unroll
            for (int t = 0; t < 2; t++) ax[w + 12 * (8 + t)] = a[t];
        }
    }
    if (w < 8) {   // extra tokens 120..127
        int l = 120 + w;
        int rb = tok[l] * 50;
        float4 v0 = __ldg(&we4[rb + lane]);
        float4 v1 = hi ? __ldg(&we4[rb + 32 + lane]) : make_float4(0, 0, 0, 0);
        e4[l * 50 + lane] = v0;
        if (hi) e4[l * 50 + 32 + lane] = v1;
        float a = warp_sum(dot4(v0, qv0) + dot4(v1, qv1));
        if (lane == 0) ax[l] = a;
    }
    __syncthreads();

    // -------- softmax over 128 tokens (warp 0) --------
    if (w == 0) {
        float v0 = ax[lane], v1 = ax[lane + 32], v2 = ax[lane + 64], v3 = ax[lane + 96];
        float m = fmaxf(fmaxf(v0, v1), fmaxf(v2, v3));
        #pragma unroll
        for (int o = 16; o; o >>= 1) m = fmaxf(m, __shfl_xor_sync(0xffffffffu, m, o));
        v0 = expf(v0 - m); v1 = expf(v1 - m); v2 = expf(v2 - m); v3 = expf(v3 - m);
        float s = v0 + v1 + v2 + v3;
        #pragma unroll
        for (int o = 16; o; o >>= 1) s += __shfl_xor_sync(0xffffffffu, s, o);
        float inv = 1.f / s;
        ax[lane] = v0 * inv; ax[lane + 32] = v1 * inv;
        ax[lane + 64] = v2 * inv; ax[lane + 96] = v3 * inv;
    }
    __syncthreads();

    // -------- z_s from SMEM tile (reshape trick: z[d] = e_flat[d*128 .. +127].ax)
    {
        const float4* ax4 = (const float4*)ax;
        const float4* ec4 = (const float4*)e;
        float4 av = ax4[lane];
        #pragma unroll
        for (int i0 = 0; i0 < 16; i0 += 4) {
            float a[4];
            #pragma unroll
            for (int k = 0; k < 4; k++) {
                int d = w + 12 * (i0 + k);
                a[k] = dot4(ec4[d * 32 + lane], av);
            }
            #pragma unroll
            for (int k = 0; k < 4; k++) a[k] = warp_sum(a[k]);
            if (lane == 0) {
                #pragma unroll
                for (int k = 0; k < 4; k++) zs[w + 12 * (i0 + k)] = a[k];
            }
        }
        if (w < 8) {
            int d = 192 + w;
            float a = warp_sum(dot4(ec4[d * 32 + lane], av));
            if (lane == 0) zs[d] = a;
        }
    }
    __syncthreads();

    // -------- logits = z_s @ W_w^T + W_b --------
    {
        const float4* zs4 = (const float4*)zs;
        float4 zv0 = zs4[lane];
        float4 zv1 = hi ? zs4[32 + lane] : make_float4(0, 0, 0, 0);
        #pragma unroll
        for (int j = 0; j < 3; j++) {
            int a = w + 12 * j;
            if (a < AASP) {
                const float4* wr = (const float4*)(Ww + a * DW);
                float acc = dot4(__ldg(&wr[lane]), zv0);
                if (hi) acc += dot4(__ldg(&wr[32 + lane]), zv1);
                acc = warp_sum(acc);
                if (lane == 0) p[a] = acc + Wb[a];
            }
        }
    }
    __syncthreads();

    // -------- softmax over A=32 (warp 0) --------
    if (w == 0) {
        float v = p[lane];
        float m = v;
        #pragma unroll
        for (int o = 16; o; o >>= 1) m = fmaxf(m, __shfl_xor_sync(0xffffffffu, m, o));
        float ex = expf(v - m);
        float s = ex;
        #pragma unroll
        for (int o = 16; o; o >>= 1) s += __shfl_xor_sync(0xffffffffu, s, o);
        p[lane] = ex / s;
    }
    __syncthreads();

    // -------- r_s = p @ T_w^T ; negatives direct; 13 fused dots --------
    float rsv = 0.f, zsv = 0.f, ng[NNEG];
    #pragma unroll
    for (int k = 0; k < NNEG; k++) ng[k] = 0.f;
    if (tid < DW) {
        const float4* T4 = (const float4*)(Tw + tid * AASP);
        float acc = 0.f;
        #pragma unroll
        for (int j = 0; j < 8; j++) {
            float4 t = __ldg(&T4[j]);
            acc += t.x * p[j * 4 + 0] + t.y * p[j * 4 + 1]
                 + t.z * p[j * 4 + 2] + t.w * p[j * 4 + 3];
        }
        g_rs[n * DW + tid] = acc;
        rsv = acc;
        zsv = zs[tid];
        #pragma unroll
        for (int k = 0; k < NNEG; k++)
            ng[k] = __ldg(&rneg[(n * NNEG + k) * DW + tid]);
    }

    float v[13];
    v[0] = zsv * zsv; v[1] = rsv * rsv; v[2] = zsv * rsv;
    #pragma unroll
    for (int k = 0; k < NNEG; k++) { v[3 + k] = ng[k] * ng[k]; v[8 + k] = ng[k] * rsv; }
    #pragma unroll
    for (int x = 0; x < 13; x++) v[x] = warp_sum(v[x]);
    if (lane == 0) {
        #pragma unroll
        for (int x = 0; x < 13; x++) part[w * 13 + x] = v[x];
    }
    __syncthreads();
    if (w == 0 && lane < 13) {
        float s = 0.f;
        #pragma unroll
        for (int k = 0; k < 12; k++) s += part[k * 13 + lane];
        tot[lane] = s;
    }
    __syncthreads();
    if (tid == 0) {
        float nz = fmaxf(sqrtf(tot[0]), 1e-12f);
        float nr = fmaxf(sqrtf(tot[1]), 1e-12f);
        float c1 = tot[2] / (nz * nr);
        float h = 0.f;
        #pragma unroll
        for (int k = 0; k < NNEG; k++) {
            float c2 = tot[8 + k] / (fmaxf(sqrtf(tot[3 + k]), 1e-12f) * nr);
            h += fmaxf(0.f, c2 - c1);
        }
        g_hinge[n] = h;
    }
}

// ---------------- K3: fused segment means + prediction ------------------------
// Block b: u-mean and i-mean rows + dot product -> g_sq[b]. No u/i round-trip.
__global__ __launch_bounds__(256, 8)
void segpred(const int* __restrict__ uhi, const int* __restrict__ usi,
             const int* __restrict__ ihi, const int* __restrict__ isi,
             const float* __restrict__ label, int F) {
    int b = blockIdx.x;
    int tid = threadIdx.x, w = tid >> 5, lane = tid & 31;
    __shared__ int bnd[4];
    __shared__ float red[8];
    if (tid < 2) {
        const int* seg = tid ? isi : usi;
        int lo = 0, hi = F;
        while (lo < hi) { int m = (lo + hi) >> 1; if (seg[m] < b) lo = m + 1; else hi = m; }
        bnd[tid * 2] = lo;
        int lo2 = lo, hi2 = F;
        while (lo2 < hi2) { int m = (lo2 + hi2) >> 1; if (seg[m] < b + 1) lo2 = m + 1; else hi2 = m; }
        bnd[tid * 2 + 1] = lo2;
    }
    __syncthreads();

    float prod = 0.f;
    int d = tid;
    if (d < DW) {
        float um, im;
        {
            int lo = bnd[0], cnt = bnd[1] - bnd[0];
            float s0 = 0.f, s1 = 0.f, s2 = 0.f, s3 = 0.f;
            int j = 0;
            for (; j + 4 <= cnt; j += 4) {
                s0 += g_rs[uhi[lo + j] * DW + d];
                s1 += g_rs[uhi[lo + j + 1] * DW + d];
                s2 += g_rs[uhi[lo + j + 2] * DW + d];
                s3 += g_rs[uhi[lo + j + 3] * DW + d];
            }
            for (; j < cnt; j++) s0 += g_rs[uhi[lo + j] * DW + d];
            um = ((s0 + s1) + (s2 + s3)) / (float)cnt;
        }
        {
            int lo = bnd[2], cnt = bnd[3] - bnd[2];
            float s0 = 0.f, s1 = 0.f, s2 = 0.f, s3 = 0.f;
            int j = 0;
            for (; j + 4 <= cnt; j += 4) {
                s0 += g_rs[ihi[lo + j] * DW + d];
                s1 += g_rs[ihi[lo + j + 1] * DW + d];
                s2 += g_rs[ihi[lo + j + 2] * DW + d];
                s3 += g_rs[ihi[lo + j + 3] * DW + d];
            }
            for (; j < cnt; j++) s0 += g_rs[ihi[lo + j] * DW + d];
            im = ((s0 + s1) + (s2 + s3)) / (float)cnt;
        }
        prod = um * im;
    }
    float s = warp_sum(prod);
    if (lane == 0) red[w] = s;
    __syncthreads();
    if (tid == 0) {
        float t = 0.f;
        #pragma unroll
        for (int k = 0; k < 8; k++) t += red[k];
        float e = t + 3.5f - label[b];
        g_sq[b] = e * e;
    }
}

// ---------------- K4: final reductions ----------------------------------------
__global__ __launch_bounds__(1024, 1)
void finkern(float* __restrict__ out) {
    __shared__ float sc[32];
    int tid = threadIdx.x, w = tid >> 5, lane = tid & 31;

    float s = 0.f;
    for (int i = tid; i < NREV; i += 1024) s += g_hinge[i];
    s = warp_sum(s);
    if (lane == 0) sc[w] = s;
    __syncthreads();
    float hs = 0.f;
    if (tid == 0) for (int k = 0; k < 32; k++) hs += sc[k];
    __syncthreads();

    float s2 = 0.f;
    for (int i = tid; i < BUSR; i += 1024) s2 += g_sq[i];
    s2 = warp_sum(s2);
    if (lane == 0) sc[w] = s2;
    __syncthreads();
    if (tid == 0) {
        float rsum = 0.f;
        for (int k = 0; k < 32; k++) rsum += sc[k];
        float rating = rsum / (float)BUSR;
        float J = hs / (float)(NREV * NNEG);
        float abae = g_U[0] + J;
        out[0] = rating + abae;
        out[1] = rating;
        out[2] = abae;
    }
}

// ---------------- launch ------------------------------------------------------
extern "C" void kernel_launch(void* const* d_in, const int* in_sizes, int n_in,
                              void* d_out, int out_size) {
    const int*   hist  = (const int*)d_in[0];
    const float* rpos  = (const float*)d_in[1];
    const float* rneg  = (const float*)d_in[2];
    const float* label = (const float*)d_in[5];
    const int*   uhi   = (const int*)d_in[6];
    const int*   usi   = (const int*)d_in[7];
    const int*   ihi   = (const int*)d_in[8];
    const int*   isi   = (const int*)d_in[9];
    const float* wemb  = (const float*)d_in[10];
    const float* Mw    = (const float*)d_in[11];
    const float* Ww    = (const float*)d_in[12];
    const float* Wb    = (const float*)d_in[13];
    const float* Tw    = (const float*)d_in[14];
    float* out = (float*)d_out;
    int F = in_sizes[6];

    const int SMEM_QK   = (DW * DW + 32 * DW) * 4;   // 185600 B
    const int SMEM_MAIN = SM_WORDS * 4;              // 105840 B
    cudaFuncSetAttribute(qk, cudaFuncAttributeMaxDynamicSharedMemorySize, SMEM_QK);
    cudaFuncSetAttribute(mainkern, cudaFuncAttributeMaxDynamicSharedMemorySize, SMEM_MAIN);

    qk<<<NREV / 32, 256, SMEM_QK>>>(rpos, Mw);
    mainkern<<<NREV + 1, 384, SMEM_MAIN>>>(hist, wemb, rneg, Ww, Wb, Tw);
    segpred<<<BUSR, 256>>>(uhi, usi, ihi, isi, label, F);
    finkern<<<1, 1024>>>(out);
}

// round 6
// speedup vs baseline: 1.2343x; 1.2343x over previous
#include <cuda_runtime.h>
#include <cuda_bf16.h>
#include <math.h>

#define NREV 4096
#define LTOK 128
#define DW   200
#define AASP 32
#define NNEG 5
#define BUSR 1024

// ---------------- scratch (device globals) -----------------------------------
__device__ __align__(16) float g_q[NREV * DW];
__device__ __align__(16) float g_rs[NREV * DW];
__device__ float g_hinge[NREV];
__device__ float g_sq[BUSR];
__device__ float g_U[1];

__device__ __forceinline__ float dot4(float4 a, float4 b) {
    return a.x * b.x + a.y * b.y + a.z * b.z + a.w * b.w;
}
__device__ __forceinline__ float warp_sum(float v) {
    #pragma unroll
    for (int o = 16; o; o >>= 1) v += __shfl_down_sync(0xffffffffu, v, o);
    return v;
}
__device__ __forceinline__ uint2 pack_bf16x4(float4 v) {
    __nv_bfloat162 a = __float22bfloat162_rn(make_float2(v.x, v.y));
    __nv_bfloat162 b = __float22bfloat162_rn(make_float2(v.z, v.w));
    uint2 u;
    u.x = *(unsigned int*)&a;
    u.y = *(unsigned int*)&b;
    return u;
}

// ---------------- K1: q = rev_pos @ M_w (vectorized) -------------------------
__global__ __launch_bounds__(256, 1)
void qk(const float* __restrict__ rp, const float* __restrict__ Mw) {
    extern __shared__ float sm[];
    float* Ms  = sm;            // 40000
    float* rps = sm + DW * DW;  // 6400
    int tid = threadIdx.x, w = tid >> 5, lane = tid & 31;
    for (int i = tid; i < DW * DW; i += 256) Ms[i] = Mw[i];
    int n0 = blockIdx.x * 32;
    for (int i = tid; i < 32 * DW; i += 256) rps[i] = rp[n0 * DW + i];
    __syncthreads();

    const float4* Ms4  = (const float4*)Ms;
    const float4* rps4 = (const float4*)rps;
    bool hi = (lane < 18);

    float4 acc[4][2];
    #pragma unroll
    for (int j = 0; j < 4; j++) {
        acc[j][0] = make_float4(0, 0, 0, 0);
        acc[j][1] = make_float4(0, 0, 0, 0);
    }

    for (int d2b = 0; d2b < 50; d2b++) {
        float4 r4[4];
        #pragma unroll
        for (int j = 0; j < 4; j++) r4[j] = rps4[(w * 4 + j) * 50 + d2b];
        #pragma unroll
        for (int s = 0; s < 4; s++) {
            int d2 = d2b * 4 + s;
            float4 m0 = Ms4[d2 * 50 + lane];
            float4 m1 = hi ? Ms4[d2 * 50 + 32 + lane] : make_float4(0, 0, 0, 0);
            #pragma unroll
            for (int j = 0; j < 4; j++) {
                float r = (s == 0) ? r4[j].x : (s == 1) ? r4[j].y : (s == 2) ? r4[j].z : r4[j].w;
                acc[j][0].x += r * m0.x; acc[j][0].y += r * m0.y;
                acc[j][0].z += r * m0.z; acc[j][0].w += r * m0.w;
                acc[j][1].x += r * m1.x; acc[j][1].y += r * m1.y;
                acc[j][1].z += r * m1.z; acc[j][1].w += r * m1.w;
            }
        }
    }
    float4* gq4 = (float4*)g_q;
    #pragma unroll
    for (int j = 0; j < 4; j++) {
        int row = (n0 + w * 4 + j) * 50;
        gq4[row + lane] = acc[j][0];
        if (hi) gq4[row + 32 + lane] = acc[j][1];
    }
}

// ---------------- K2: fused per-review ABAE, bf16 SMEM tile, occ 4 ------------
// 256 threads, 4 CTAs/SM. SMEM (floats view, 13608 words = 54432 B):
//   e_bf16 [0..12799] as uint2/bf16x2 (51200 B) | qs 12800 | ax 13000 |
//   zs 13128 | p 13328 | part 13360 (8*13) | tot 13464 | tok(int) 13480..13607
#define SM_WORDS 13608

__global__ __launch_bounds__(256, 4)
void mainkern(const int* __restrict__ hist, const float* __restrict__ wemb,
              const float* __restrict__ rneg, const float* __restrict__ Ww,
              const float* __restrict__ Wb, const float* __restrict__ Tw) {
    extern __shared__ float sm[];
    int n = blockIdx.x;
    int tid = threadIdx.x, w = tid >> 5, lane = tid & 31;

    // -------- extra block: U_loss --------
    if (n == NREV) {
        float* Ts  = sm;          // 6400
        float* nrm = sm + 6400;   // 32
        float* red = sm + 6432;   // 8
        for (int i = tid; i < DW * AASP; i += 256) Ts[i] = Tw[i];
        __syncthreads();
        if (tid < AASP) {
            float s = 0.f;
            for (int d = 0; d < DW; d++) { float v = Ts[d * AASP + tid]; s += v * v; }
            nrm[tid] = fmaxf(sqrtf(s), 1e-12f);
        }
        __syncthreads();
        float part = 0.f;
        for (int pr = tid; pr < AASP * AASP; pr += 256) {
            int a = pr >> 5, b = pr & 31;
            float s = 0.f;
            for (int d = 0; d < DW; d++) s += Ts[d * AASP + a] * Ts[d * AASP + b];
            float g = s / (nrm[a] * nrm[b]);
            float diff = g - ((a == b) ? 1.f : 0.f);
            part += diff * diff;
        }
        float v = warp_sum(part);
        if (lane == 0) red[w] = v;
        __syncthreads();
        if (tid == 0) {
            float t = 0.f;
            for (int k = 0; k < 8; k++) t += red[k];
            g_U[0] = t / (float)(AASP * AASP);
        }
        return;
    }

    uint2* eb2  = (uint2*)sm;          // bf16x4 per uint2; same index as float4 view
    float* qs   = sm + 12800;
    float* ax   = sm + 13000;
    float* zs   = sm + 13128;
    float* p    = sm + 13328;
    float* part = sm + 13360;
    float* tot  = sm + 13464;
    int*   tok  = (int*)(sm + 13480);

    if (tid < LTOK) tok[tid] = hist[n * LTOK + tid];
    if (tid < DW)   qs[tid]  = g_q[n * DW + tid];
    __syncthreads();

    bool hi = (lane < 18);
    const float4* qs4 = (const float4*)qs;
    float4 qv0 = qs4[lane];
    float4 qv1 = hi ? qs4[32 + lane] : make_float4(0, 0, 0, 0);
    const float4* we4 = (const float4*)wemb;

    // -------- single gather + dx (fp32 exact) + bf16 tile store --------
    // warp w owns tokens w*16 .. w*16+15, in batches of 4 (8 loads in flight)
    #pragma unroll
    for (int t0 = 0; t0 < 16; t0 += 4) {
        float4 v0[4], v1[4];
        #pragma unroll
        for (int t = 0; t < 4; t++) {
            int rb = tok[w * 16 + t0 + t] * 50;
            v0[t] = __ldg(&we4[rb + lane]);
            v1[t] = hi ? __ldg(&we4[rb + 32 + lane]) : make_float4(0, 0, 0, 0);
        }
        float a[4];
        #pragma unroll
        for (int t = 0; t < 4; t++) {
            int l = w * 16 + t0 + t;
            eb2[l * 50 + lane] = pack_bf16x4(v0[t]);
            if (hi) eb2[l * 50 + 32 + lane] = pack_bf16x4(v1[t]);
            a[t] = dot4(v0[t], qv0) + dot4(v1[t], qv1);
        }
        #pragma unroll
        for (int t = 0; t < 4; t++) a[t] = warp_sum(a[t]);
        if (lane == 0) {
            #pragma unroll
            for (int t = 0; t < 4; t++) ax[w * 16 + t0 + t] = a[t];
        }
    }
    __syncthreads();

    // -------- softmax over 128 tokens (warp 0) --------
    if (w == 0) {
        float v0 = ax[lane], v1 = ax[lane + 32], v2 = ax[lane + 64], v3 = ax[lane + 96];
        float m = fmaxf(fmaxf(v0, v1), fmaxf(v2, v3));
        #pragma unroll
        for (int o = 16; o; o >>= 1) m = fmaxf(m, __shfl_xor_sync(0xffffffffu, m, o));
        v0 = expf(v0 - m); v1 = expf(v1 - m); v2 = expf(v2 - m); v3 = expf(v3 - m);
        float s = v0 + v1 + v2 + v3;
        #pragma unroll
        for (int o = 16; o; o >>= 1) s += __shfl_xor_sync(0xffffffffu, s, o);
        float inv = 1.f / s;
        ax[lane] = v0 * inv; ax[lane + 32] = v1 * inv;
        ax[lane + 64] = v2 * inv; ax[lane + 96] = v3 * inv;
    }
    __syncthreads();

    // -------- z_s from bf16 SMEM tile (reshape trick, flat slices) --------
    // z[d] = sum over flat pos d*128 .. d*128+127 ; lane covers pos d*128+lane*4
    {
        const float4* ax4 = (const float4*)ax;
        float4 av = ax4[lane];
        #pragma unroll
        for (int j0 = 0; j0 < 24; j0 += 4) {
            float a[4];
            #pragma unroll
            for (int k = 0; k < 4; k++) {
                int d = w + 8 * (j0 + k);
                uint2 u = eb2[d * 32 + lane];
                float2 f0 = __bfloat1622float2(*(__nv_bfloat162*)&u.x);
                float2 f1 = __bfloat1622float2(*(__nv_bfloat162*)&u.y);
                a[k] = f0.x * av.x + f0.y * av.y + f1.x * av.z + f1.y * av.w;
            }
            #pragma unroll
            for (int k = 0; k < 4; k++) a[k] = warp_sum(a[k]);
            if (lane == 0) {
                #pragma unroll
                for (int k = 0; k < 4; k++) zs[w + 8 * (j0 + k)] = a[k];
            }
        }
        {   // leftover d = 192 + w
            int d = 192 + w;
            uint2 u = eb2[d * 32 + lane];
            float2 f0 = __bfloat1622float2(*(__nv_bfloat162*)&u.x);
            float2 f1 = __bfloat1622float2(*(__nv_bfloat162*)&u.y);
            float a = warp_sum(f0.x * av.x + f0.y * av.y + f1.x * av.z + f1.y * av.w);
            if (lane == 0) zs[d] = a;
        }
    }
    __syncthreads();

    // -------- logits = z_s @ W_w^T + W_b (warp w: aspects w+8j) --------
    {
        const float4* zs4 = (const float4*)zs;
        float4 zv0 = zs4[lane];
        float4 zv1 = hi ? zs4[32 + lane] : make_float4(0, 0, 0, 0);
        #pragma unroll
        for (int j = 0; j < 4; j++) {
            int a = w + 8 * j;
            const float4* wr = (const float4*)(Ww + a * DW);
            float acc = dot4(__ldg(&wr[lane]), zv0);
            if (hi) acc += dot4(__ldg(&wr[32 + lane]), zv1);
            acc = warp_sum(acc);
            if (lane == 0) p[a] = acc + Wb[a];
        }
    }
    __syncthreads();

    // -------- softmax over A=32 (warp 0) --------
    if (w == 0) {
        float v = p[lane];
        float m = v;
        #pragma unroll
        for (int o = 16; o; o >>= 1) m = fmaxf(m, __shfl_xor_sync(0xffffffffu, m, o));
        float ex = expf(v - m);
        float s = ex;
        #pragma unroll
        for (int o = 16; o; o >>= 1) s += __shfl_xor_sync(0xffffffffu, s, o);
        p[lane] = ex / s;
    }
    __syncthreads();

    // -------- r_s = p @ T_w^T ; negatives direct; 13 fused dots --------
    float rsv = 0.f, zsv = 0.f, ng[NNEG];
    #pragma unroll
    for (int k = 0; k < NNEG; k++) ng[k] = 0.f;
    if (tid < DW) {
        #pragma unroll
        for (int k = 0; k < NNEG; k++)
            ng[k] = __ldg(&rneg[(n * NNEG + k) * DW + tid]);
        const float4* T4 = (const float4*)(Tw + tid * AASP);
        float acc = 0.f;
        #pragma unroll
        for (int j = 0; j < 8; j++) {
            float4 t = __ldg(&T4[j]);
            acc += t.x * p[j * 4 + 0] + t.y * p[j * 4 + 1]
                 + t.z * p[j * 4 + 2] + t.w * p[j * 4 + 3];
        }
        g_rs[n * DW + tid] = acc;
        rsv = acc;
        zsv = zs[tid];
    }

    float v[13];
    v[0] = zsv * zsv; v[1] = rsv * rsv; v[2] = zsv * rsv;
    #pragma unroll
    for (int k = 0; k < NNEG; k++) { v[3 + k] = ng[k] * ng[k]; v[8 + k] = ng[k] * rsv; }
    #pragma unroll
    for (int x = 0; x < 13; x++) v[x] = warp_sum(v[x]);
    if (lane == 0) {
        #pragma unroll
        for (int x = 0; x < 13; x++) part[w * 13 + x] = v[x];
    }
    __syncthreads();
    if (w == 0 && lane < 13) {
        float s = 0.f;
        #pragma unroll
        for (int k = 0; k < 8; k++) s += part[k * 13 + lane];
        tot[lane] = s;
    }
    __syncthreads();
    if (tid == 0) {
        float nz = fmaxf(sqrtf(tot[0]), 1e-12f);
        float nr = fmaxf(sqrtf(tot[1]), 1e-12f);
        float c1 = tot[2] / (nz * nr);
        float h = 0.f;
        #pragma unroll
        for (int k = 0; k < NNEG; k++) {
            float c2 = tot[8 + k] / (fmaxf(sqrtf(tot[3 + k]), 1e-12f) * nr);
            h += fmaxf(0.f, c2 - c1);
        }
        g_hinge[n] = h;
    }
}

// ---------------- K3: fused segment means + prediction ------------------------
__global__ __launch_bounds__(256, 8)
void segpred(const int* __restrict__ uhi, const int* __restrict__ usi,
             const int* __restrict__ ihi, const int* __restrict__ isi,
             const float* __restrict__ label, int F) {
    int b = blockIdx.x;
    int tid = threadIdx.x, w = tid >> 5, lane = tid & 31;
    __shared__ int bnd[4];
    __shared__ float red[8];
    if (tid < 2) {
        const int* seg = tid ? isi : usi;
        int lo = 0, hi = F;
        while (lo < hi) { int m = (lo + hi) >> 1; if (seg[m] < b) lo = m + 1; else hi = m; }
        bnd[tid * 2] = lo;
        int lo2 = lo, hi2 = F;
        while (lo2 < hi2) { int m = (lo2 + hi2) >> 1; if (seg[m] < b + 1) lo2 = m + 1; else hi2 = m; }
        bnd[tid * 2 + 1] = lo2;
    }
    __syncthreads();

    float prod = 0.f;
    int d = tid;
    if (d < DW) {
        float um, im;
        {
            int lo = bnd[0], cnt = bnd[1] - bnd[0];
            float s0 = 0.f, s1 = 0.f, s2 = 0.f, s3 = 0.f;
            int j = 0;
            for (; j + 4 <= cnt; j += 4) {
                s0 += g_rs[uhi[lo + j] * DW + d];
                s1 += g_rs[uhi[lo + j + 1] * DW + d];
                s2 += g_rs[uhi[lo + j + 2] * DW + d];
                s3 += g_rs[uhi[lo + j + 3] * DW + d];
            }
            for (; j < cnt; j++) s0 += g_rs[uhi[lo + j] * DW + d];
            um = ((s0 + s1) + (s2 + s3)) / (float)cnt;
        }
        {
            int lo = bnd[2], cnt = bnd[3] - bnd[2];
            float s0 = 0.f, s1 = 0.f, s2 = 0.f, s3 = 0.f;
            int j = 0;
            for (; j + 4 <= cnt; j += 4) {
                s0 += g_rs[ihi[lo + j] * DW + d];
                s1 += g_rs[ihi[lo + j + 1] * DW + d];
                s2 += g_rs[ihi[lo + j + 2] * DW + d];
                s3 += g_rs[ihi[lo + j + 3] * DW + d];
            }
            for (; j < cnt; j++) s0 += g_rs[ihi[lo + j] * DW + d];
            im = ((s0 + s1) + (s2 + s3)) / (float)cnt;
        }
        prod = um * im;
    }
    float s = warp_sum(prod);
    if (lane == 0) red[w] = s;
    __syncthreads();
    if (tid == 0) {
        float t = 0.f;
        #pragma unroll
        for (int k = 0; k < 8; k++) t += red[k];
        float e = t + 3.5f - label[b];
        g_sq[b] = e * e;
    }
}

// ---------------- K4: final reductions ----------------------------------------
__global__ __launch_bounds__(1024, 1)
void finkern(float* __restrict__ out) {
    __shared__ float sc[32];
    int tid = threadIdx.x, w = tid >> 5, lane = tid & 31;

    float s = 0.f;
    for (int i = tid; i < NREV; i += 1024) s += g_hinge[i];
    s = warp_sum(s);
    if (lane == 0) sc[w] = s;
    __syncthreads();
    float hs = 0.f;
    if (tid == 0) for (int k = 0; k < 32; k++) hs += sc[k];
    __syncthreads();

    float s2 = 0.f;
    for (int i = tid; i < BUSR; i += 1024) s2 += g_sq[i];
    s2 = warp_sum(s2);
    if (lane == 0) sc[w] = s2;
    __syncthreads();
    if (tid == 0) {
        float rsum = 0.f;
        for (int k = 0; k < 32; k++) rsum += sc[k];
        float rating = rsum / (float)BUSR;
        float J = hs / (float)(NREV * NNEG);
        float abae = g_U[0] + J;
        out[0] = rating + abae;
        out[1] = rating;
        out[2] = abae;
    }
}

// ---------------- launch ------------------------------------------------------
extern "C" void kernel_launch(void* const* d_in, const int* in_sizes, int n_in,
                              void* d_out, int out_size) {
    const int*   hist  = (const int*)d_in[0];
    const float* rpos  = (const float*)d_in[1];
    const float* rneg  = (const float*)d_in[2];
    const float* label = (const float*)d_in[5];
    const int*   uhi   = (const int*)d_in[6];
    const int*   usi   = (const int*)d_in[7];
    const int*   ihi   = (const int*)d_in[8];
    const int*   isi   = (const int*)d_in[9];
    const float* wemb  = (const float*)d_in[10];
    const float* Mw    = (const float*)d_in[11];
    const float* Ww    = (const float*)d_in[12];
    const float* Wb    = (const float*)d_in[13];
    const float* Tw    = (const float*)d_in[14];
    float* out = (float*)d_out;
    int F = in_sizes[6];

    const int SMEM_QK   = (DW * DW + 32 * DW) * 4;   // 185600 B
    const int SMEM_MAIN = SM_WORDS * 4;              // 54432 B
    cudaFuncSetAttribute(qk, cudaFuncAttributeMaxDynamicSharedMemorySize, SMEM_QK);
    cudaFuncSetAttribute(mainkern, cudaFuncAttributeMaxDynamicSharedMemorySize, SMEM_MAIN);

    qk<<<NREV / 32, 256, SMEM_QK>>>(rpos, Mw);
    mainkern<<<NREV + 1, 256, SMEM_MAIN>>>(hist, wemb, rneg, Ww, Wb, Tw);
    segpred<<<BUSR, 256>>>(uhi, usi, ihi, isi, label, F);
    finkern<<<1, 1024>>>(out);
}